// round 13
// baseline (speedup 1.0000x reference)
#include <cuda_runtime.h>
#include <cuda_fp16.h>
#include <mma.h>
#include <math.h>
#include <stddef.h>
#include <stdint.h>

using namespace nvcuda;

#define B    16
#define CIN  512
#define COUT 512
#define HH   64
#define WW   64
#define SD   512
#define EPS  1e-8f

#define MOD_SCALE  0.04419417382415922f   // 1/sqrt(512)
#define CONV_SCALE 0.014731391274719738f  // 1/sqrt(512*9)

// padded, channel-last, scaled input: [B][66][66][512] fp16
#define XP 66
static __device__ __half g_xs[(size_t)B * XP * XP * CIN];
// weights channel-last per tap: [9][512 oc][512 ci] fp16
static __device__ __half g_wt[9 * COUT * CIN];
__device__ float g_s[B * CIN];
__device__ float g_demod[B * COUT];

__device__ __forceinline__ uint32_t smem_u32(const void* p) {
    uint32_t a;
    asm("{ .reg .u64 t; cvta.to.shared.u64 t, %1; cvt.u32.u64 %0, t; }"
        : "=r"(a) : "l"(p));
    return a;
}

#define MBAR_INIT(a, c) \
    asm volatile("mbarrier.init.shared.b64 [%0], %1;" :: "r"(a), "r"((uint32_t)(c)) : "memory")
#define MBAR_ARRIVE(a) \
    asm volatile("mbarrier.arrive.shared.b64 _, [%0];" :: "r"(a) : "memory")
#define MBAR_WAIT(a, ph) do {                                                        \
    asm volatile("{\n\t.reg .pred P1;\n\t"                                           \
        "WL%=:\n\tmbarrier.try_wait.parity.acquire.cta.shared::cta.b64 P1, [%0], %1, 0x989680;\n\t" \
        "@P1 bra.uni WD%=;\n\tbra.uni WL%=;\n\tWD%=:\n\t}"                           \
        :: "r"(a), "r"((uint32_t)(ph)) : "memory"); } while (0)
#define CPASYNC_MBAR_ARRIVE_NOINC(a) \
    asm volatile("cp.async.mbarrier.arrive.noinc.shared.b64 [%0];" :: "r"(a) : "memory")

// ---------------------------------------------------------------------------
// Kernel 1: s[b][i] = MOD_SCALE * (style[b,:] . mod_weight[i,:]) + mod_bias[i]
// grid = 64 blocks x 8 i's (one warp per i); style loaded 64x, not 512x.
// ---------------------------------------------------------------------------
__global__ __launch_bounds__(256) void mod_kernel(
    const float* __restrict__ style, const float* __restrict__ mw,
    const float* __restrict__ mb)
{
    const int i0 = blockIdx.x * 8;
    const int t = threadIdx.x;
    __shared__ float sh_style[B * SD];   // 32 KB
    __shared__ float sh_w[8 * SD];       // 16 KB
    for (int idx = t; idx < B * SD; idx += 256) sh_style[idx] = style[idx];
    for (int idx = t; idx < 8 * SD; idx += 256)
        sh_w[idx] = mw[(size_t)i0 * SD + idx];
    __syncthreads();

    const int w = t >> 5, lane = t & 31;
    const int i = i0 + w;
    float acc[B];
#pragma unroll
    for (int b = 0; b < B; b++) acc[b] = 0.f;
    for (int d = lane; d < SD; d += 32) {
        const float wv = sh_w[w * SD + d];
#pragma unroll
        for (int b = 0; b < B; b++) acc[b] += wv * sh_style[b * SD + d];
    }
#pragma unroll
    for (int off = 16; off > 0; off >>= 1)
#pragma unroll
        for (int b = 0; b < B; b++)
            acc[b] += __shfl_down_sync(0xffffffffu, acc[b], off);
    if (lane == 0) {
        const float bias = mb[i];
#pragma unroll
        for (int b = 0; b < B; b++)
            g_s[b * CIN + i] = acc[b] * MOD_SCALE + bias;
    }
}

// ---------------------------------------------------------------------------
// Kernel 2: demod[b][oc] = rsqrt(CONV_SCALE^2 * sum_i wsq[oc,i]*s[b,i]^2 + eps)
// ---------------------------------------------------------------------------
__global__ __launch_bounds__(256) void demod_kernel(const float* __restrict__ cw)
{
    const int oc = blockIdx.x, t = threadIdx.x;
    __shared__ float red[8][B];
    float acc[B];
#pragma unroll
    for (int b = 0; b < B; b++) acc[b] = 0.f;
    for (int i = t; i < CIN; i += 256) {
        const float* wp = cw + ((size_t)oc * CIN + i) * 9;
        float wsq = 0.f;
#pragma unroll
        for (int k = 0; k < 9; k++) { const float v = wp[k]; wsq += v * v; }
#pragma unroll
        for (int b = 0; b < B; b++) {
            const float s = g_s[b * CIN + i];
            acc[b] += wsq * s * s;
        }
    }
#pragma unroll
    for (int off = 16; off > 0; off >>= 1)
#pragma unroll
        for (int b = 0; b < B; b++)
            acc[b] += __shfl_down_sync(0xffffffffu, acc[b], off);
    const int warp = t >> 5, lane = t & 31;
    if (lane == 0)
#pragma unroll
        for (int b = 0; b < B; b++) red[warp][b] = acc[b];
    __syncthreads();
    if (t < B) {
        float v = 0.f;
#pragma unroll
        for (int w = 0; w < 8; w++) v += red[w][t];
        g_demod[t * COUT + oc] = rsqrtf(CONV_SCALE * CONV_SCALE * v + EPS);
    }
}

// ---------------------------------------------------------------------------
// Kernel 3 (fused): weight transpose (coalesced via SMEM staging) + borders.
// Blocks [0, 512): oc-block — stage cw[oc] (4608 floats) in SMEM, emit
//   g_wt[tap][oc][ci] as half2 runs (coalesced stores).
// Blocks [512, 512+4160): zero one 512-ch border row.
// ---------------------------------------------------------------------------
#define WSPLIT_BLOCKS COUT                     // 512
#define BORDER_BLOCKS (B * 260)                // 4160
__global__ __launch_bounds__(256) void prep_kernel(const float* __restrict__ cw)
{
    if (blockIdx.x < WSPLIT_BLOCKS) {
        const int oc = blockIdx.x;
        __shared__ float sw[CIN * 9];          // 18 KB
        const float* src = cw + (size_t)oc * (CIN * 9);
        for (int k = threadIdx.x; k < CIN * 9; k += 256) sw[k] = src[k];
        __syncthreads();
#pragma unroll
        for (int it = 0; it < 9; it++) {       // 2304 half2 = 9 taps x 256 pairs
            const int k = it * 256 + threadIdx.x;
            const int tap = k >> 8, ci = (k & 255) * 2;
            *(__half2*)&g_wt[((size_t)tap << 18) + ((size_t)oc << 9) + ci] =
                __floats2half2_rn(sw[ci * 9 + tap], sw[(ci + 1) * 9 + tap]);
        }
    } else {
        int i = blockIdx.x - WSPLIT_BLOCKS;   // 0..4159
        int b = i / 260, r = i % 260;
        int h, w;
        if      (r <  66) { h = 0;           w = r;        }
        else if (r < 132) { h = 65;          w = r - 66;   }
        else if (r < 196) { h = r - 132 + 1; w = 0;        }
        else              { h = r - 196 + 1; w = 65;       }
        size_t base = (((size_t)b * XP + h) * XP + w) * CIN;
        *(uint32_t*)((char*)g_xs + base * 2 + threadIdx.x * 4) = 0u;
    }
}

// ---------------------------------------------------------------------------
// Kernel 4: transpose + scale:  xs[b][h+1][w+1][ci] = fp16(CONV_SCALE*s*x)
// float4 reads, __half2 stores (full-width warp transactions).
// ---------------------------------------------------------------------------
__global__ __launch_bounds__(256) void xtrans_kernel(const float* __restrict__ x)
{
    const int cic = blockIdx.x, h = blockIdx.y, b = blockIdx.z;
    const int tid = threadIdx.x;
    const int ci0 = cic * 64;
    __shared__ float sT[64 * 65];
    __shared__ float sS[64];
    if (tid < 64) sS[tid] = CONV_SCALE * g_s[b * CIN + ci0 + tid];
#pragma unroll
    for (int it = 0; it < 4; it++) {           // 1024 float4 ops = 64 rows x 16
        int idx = it * 256 + tid;
        int cl = idx >> 4, wq = idx & 15;
        float4 v = *(const float4*)&x[(((size_t)(b * CIN + ci0 + cl)) * HH + h) * WW + wq * 4];
        float* d = &sT[cl * 65 + wq * 4];
        d[0] = v.x; d[1] = v.y; d[2] = v.z; d[3] = v.w;
    }
    __syncthreads();
#pragma unroll
    for (int it = 0; it < 8; it++) {           // 2048 half2 ops = 64 w x 32 pairs
        int idx = it * 256 + tid;
        int w = idx >> 5, clp = idx & 31;
        int cl = clp * 2;
        float v0 = sS[cl]     * sT[cl * 65 + w];
        float v1 = sS[cl + 1] * sT[(cl + 1) * 65 + w];
        size_t dst = (((size_t)b * XP + h + 1) * XP + (w + 1)) * CIN + ci0 + cl;
        *(__half2*)&g_xs[dst] = __floats2half2_rn(v0, v1);
    }
}

// ---------------------------------------------------------------------------
// Kernel 5: main wmma (HMMA) implicit-GEMM conv, warp-specialized pipeline.
// CTA: 128 oc x 256 px (4h x 64w). 10 warps: 0-7 compute (warp tile 64x64),
// 8-9 producers (cp.async.ca + mbarrier ring, 3 slots). No __syncthreads in
// loop. fp32 accum, demod in epilogue.   [R7 exact configuration]
// ---------------------------------------------------------------------------
#define LDM 72                           // 64 halves data + 8 pad (144B rows)
#define A_BYTES (128 * LDM * 2)          // 18432
#define B_BYTES (256 * LDM * 2)          // 36864
#define STAGE_BYTES (A_BYTES + B_BYTES)  // 55296
#define NSTAGE 3
#define SMEM_DYN (NSTAGE * STAGE_BYTES)  // 165888
#define NTHREADS 320

__global__ __launch_bounds__(NTHREADS, 1) void conv_wmma_kernel(float* __restrict__ out)
{
    extern __shared__ char dynsmem[];
    __shared__ __align__(8) uint64_t sh_mbar[2 * NSTAGE];  // full[3], empty[3]

    const int tid = threadIdx.x;
    const int wid = tid >> 5;
    const int lane = tid & 31;

    const int bx = blockIdx.x;    // 16 b x 16 h-groups(4h)
    const int b  = bx >> 4;
    const int h0 = (bx & 15) * 4;
    const int oc0 = blockIdx.y * 128;

    const uint32_t s_u32 = smem_u32(dynsmem);
    const uint32_t mb_u32 = smem_u32(&sh_mbar[0]);
    // full[s] at mb_u32 + s*8, empty[s] at mb_u32 + NSTAGE*8 + s*8

    if (tid == 0) {
#pragma unroll
        for (int s = 0; s < NSTAGE; s++) {
            MBAR_INIT(mb_u32 + s * 8, 64);                // full: 64 producer threads
            MBAR_INIT(mb_u32 + NSTAGE * 8 + s * 8, 8);    // empty: 8 compute warps
        }
    }
    __syncthreads();

    if (wid >= 8) {
        // ---------------- producers (warps 8-9, 64 threads) ----------------
        const int ptid = tid - 256;              // 0..63
        int slot = 0, par = 1;                   // phase-flip trick: first NSTAGE waits pass
        for (int iter = 0; iter < 72; iter++) {
            MBAR_WAIT(mb_u32 + NSTAGE * 8 + slot * 8, par);

            const int tap = iter >> 3;
            const int ci0 = (iter & 7) * 64;
            const int kh = tap / 3, kw = tap - 3 * kh;
            const uint32_t st = s_u32 + slot * STAGE_BYTES;
            const __half* wbase = g_wt + ((size_t)tap << 18) + ci0;
            const __half* xbase = g_xs + ((((size_t)b * XP) + h0 + kh) * XP + kw) * CIN + ci0;
#pragma unroll
            for (int j = 0; j < 48; j++) {
                const int op = j * 64 + ptid;
                uint32_t dst;
                const __half* src;
                if (j < 16) {                    // A: ops 0..1023 (compile-time split)
                    const int r = op >> 3, c = op & 7;
                    dst = st + r * 144 + c * 16;
                    src = wbase + ((size_t)(oc0 + r) << 9) + c * 8;
                } else {                         // B: ops 1024..3071
                    const int idx = op - 1024;
                    const int r = idx >> 3, c = idx & 7;
                    dst = st + A_BYTES + r * 144 + c * 16;
                    src = xbase + ((size_t)((r >> 6) * XP + (r & 63)) << 9) + c * 8;
                }
                asm volatile("cp.async.ca.shared.global [%0], [%1], 16;"
                             :: "r"(dst), "l"(src));
            }
            CPASYNC_MBAR_ARRIVE_NOINC(mb_u32 + slot * 8);

            slot++; if (slot == NSTAGE) { slot = 0; par ^= 1; }
        }
    } else {
        // ---------------- consumers (warps 0-7) ----------------
        const int wm = wid & 1;       // warp M block (64 oc)
        const int wn = wid >> 1;      // warp N block (64 px)

        wmma::fragment<wmma::accumulator, 16, 16, 16, float> c[4][4];
#pragma unroll
        for (int mt = 0; mt < 4; mt++)
#pragma unroll
            for (int nt = 0; nt < 4; nt++) wmma::fill_fragment(c[mt][nt], 0.f);

        int slot = 0, par = 0;
        for (int iter = 0; iter < 72; iter++) {
            MBAR_WAIT(mb_u32 + slot * 8, par);

            const char* st = dynsmem + slot * STAGE_BYTES;
            const __half* sA = (const __half*)(st);
            const __half* sB = (const __half*)(st + A_BYTES);

#pragma unroll
            for (int ks = 0; ks < 4; ks++) {
                wmma::fragment<wmma::matrix_b, 16, 16, 16, __half, wmma::col_major> bf[4];
#pragma unroll
                for (int nt = 0; nt < 4; nt++)
                    wmma::load_matrix_sync(bf[nt], sB + (wn * 64 + nt * 16) * LDM + ks * 16, LDM);
#pragma unroll
                for (int mt = 0; mt < 4; mt++) {
                    wmma::fragment<wmma::matrix_a, 16, 16, 16, __half, wmma::row_major> af;
                    wmma::load_matrix_sync(af, sA + (wm * 64 + mt * 16) * LDM + ks * 16, LDM);
#pragma unroll
                    for (int nt = 0; nt < 4; nt++)
                        wmma::mma_sync(c[mt][nt], af, bf[nt], c[mt][nt]);
                }
            }
            if (lane == 0) MBAR_ARRIVE(mb_u32 + NSTAGE * 8 + slot * 8);

            slot++; if (slot == NSTAGE) { slot = 0; par ^= 1; }
        }

        __syncthreads();   // join producers before smem reuse

        // epilogue part 1: accum -> SMEM [128 oc][260 px]
        float* ep = (float*)dynsmem;
#pragma unroll
        for (int mt = 0; mt < 4; mt++)
#pragma unroll
            for (int nt = 0; nt < 4; nt++)
                wmma::store_matrix_sync(ep + (wm * 64 + mt * 16) * 260 + wn * 64 + nt * 16,
                                        c[mt][nt], 260, wmma::mem_row_major);
        goto epilogue_join;
    }
    __syncthreads();       // producers join here (matches consumers' first sync)
epilogue_join:
    __syncthreads();       // everyone: ep fully written

    // epilogue part 2: demod-scaled coalesced STG, all 320 threads
    {
        const float* ep = (const float*)dynsmem;
        for (int idx = tid; idx < 128 * 256; idx += NTHREADS) {
            const int oc = idx >> 8, p = idx & 255;
            const float dm = g_demod[b * COUT + oc0 + oc];
            out[(((size_t)b * COUT + oc0 + oc) * HH + h0 + (p >> 6)) * WW + (p & 63)] =
                ep[oc * 260 + p] * dm;
        }
    }
}

// ---------------------------------------------------------------------------
extern "C" void kernel_launch(void* const* d_in, const int* in_sizes, int n_in,
                              void* d_out, int out_size)
{
    const float* input       = (const float*)d_in[0];
    const float* style       = (const float*)d_in[1];
    const float* conv_weight = (const float*)d_in[2];
    const float* mod_weight  = (const float*)d_in[3];
    const float* mod_bias    = (const float*)d_in[4];
    float* out = (float*)d_out;

    mod_kernel<<<64, 256>>>(style, mod_weight, mod_bias);
    demod_kernel<<<COUT, 256>>>(conv_weight);
    prep_kernel<<<WSPLIT_BLOCKS + BORDER_BLOCKS, 256>>>(conv_weight);
    xtrans_kernel<<<dim3(8, 64, 16), 256>>>(input);

    cudaFuncSetAttribute(conv_wmma_kernel,
                         cudaFuncAttributeMaxDynamicSharedMemorySize, SMEM_DYN);
    conv_wmma_kernel<<<dim3(256, 4), NTHREADS, SMEM_DYN>>>(out);
}

// round 14
// speedup vs baseline: 1.0071x; 1.0071x over previous
#include <cuda_runtime.h>
#include <cuda_fp16.h>
#include <mma.h>
#include <math.h>
#include <stddef.h>
#include <stdint.h>

using namespace nvcuda;

#define B    16
#define CIN  512
#define COUT 512
#define HH   64
#define WW   64
#define SD   512
#define EPS  1e-8f

#define MOD_SCALE  0.04419417382415922f   // 1/sqrt(512)
#define CONV_SCALE 0.014731391274719738f  // 1/sqrt(512*9)

// padded, channel-last, scaled input: [B][66][66][512] fp16
#define XP 66
static __device__ __half g_xs[(size_t)B * XP * XP * CIN];
// weights channel-last per tap: [9][512 oc][512 ci] fp16
static __device__ __half g_wt[9 * COUT * CIN];
__device__ float g_s[B * CIN];
__device__ float g_demod[B * COUT];

__device__ __forceinline__ uint32_t smem_u32(const void* p) {
    uint32_t a;
    asm("{ .reg .u64 t; cvta.to.shared.u64 t, %1; cvt.u32.u64 %0, t; }"
        : "=r"(a) : "l"(p));
    return a;
}

#define MBAR_INIT(a, c) \
    asm volatile("mbarrier.init.shared.b64 [%0], %1;" :: "r"(a), "r"((uint32_t)(c)) : "memory")
#define MBAR_ARRIVE(a) \
    asm volatile("mbarrier.arrive.shared.b64 _, [%0];" :: "r"(a) : "memory")
#define MBAR_WAIT(a, ph) do {                                                        \
    asm volatile("{\n\t.reg .pred P1;\n\t"                                           \
        "WL%=:\n\tmbarrier.try_wait.parity.acquire.cta.shared::cta.b64 P1, [%0], %1, 0x989680;\n\t" \
        "@P1 bra.uni WD%=;\n\tbra.uni WL%=;\n\tWD%=:\n\t}"                           \
        :: "r"(a), "r"((uint32_t)(ph)) : "memory"); } while (0)
#define CPASYNC_MBAR_ARRIVE_NOINC(a) \
    asm volatile("cp.async.mbarrier.arrive.noinc.shared.b64 [%0];" :: "r"(a) : "memory")

// ---------------------------------------------------------------------------
// Kernel 1: s[b][i] = MOD_SCALE * (style[b,:] . mod_weight[i,:]) + mod_bias[i]
// grid = 64 blocks x 8 i's (one warp per i).
// ---------------------------------------------------------------------------
__global__ __launch_bounds__(256) void mod_kernel(
    const float* __restrict__ style, const float* __restrict__ mw,
    const float* __restrict__ mb)
{
    const int i0 = blockIdx.x * 8;
    const int t = threadIdx.x;
    __shared__ float sh_style[B * SD];   // 32 KB
    __shared__ float sh_w[8 * SD];       // 16 KB
    for (int idx = t; idx < B * SD; idx += 256) sh_style[idx] = style[idx];
    for (int idx = t; idx < 8 * SD; idx += 256)
        sh_w[idx] = mw[(size_t)i0 * SD + idx];
    __syncthreads();

    const int w = t >> 5, lane = t & 31;
    const int i = i0 + w;
    float acc[B];
#pragma unroll
    for (int b = 0; b < B; b++) acc[b] = 0.f;
    for (int d = lane; d < SD; d += 32) {
        const float wv = sh_w[w * SD + d];
#pragma unroll
        for (int b = 0; b < B; b++) acc[b] += wv * sh_style[b * SD + d];
    }
#pragma unroll
    for (int off = 16; off > 0; off >>= 1)
#pragma unroll
        for (int b = 0; b < B; b++)
            acc[b] += __shfl_down_sync(0xffffffffu, acc[b], off);
    if (lane == 0) {
        const float bias = mb[i];
#pragma unroll
        for (int b = 0; b < B; b++)
            g_s[b * CIN + i] = acc[b] * MOD_SCALE + bias;
    }
}

// ---------------------------------------------------------------------------
// Kernel 2 (fused): weight transpose + demod + borders. Runs AFTER mod.
// Blocks [0, 512):        wsplit per oc (SMEM-staged, coalesced)
// Blocks [512, 1024):     demod per oc
// Blocks [1024, 1024+4160): zero one 512-ch border row of g_xs
// ---------------------------------------------------------------------------
#define WSPLIT_BLOCKS COUT                     // 512
#define DEMOD_BLOCKS  COUT                     // 512
#define BORDER_BLOCKS (B * 260)                // 4160
__global__ __launch_bounds__(256) void prep_kernel(const float* __restrict__ cw)
{
    if (blockIdx.x < WSPLIT_BLOCKS) {
        const int oc = blockIdx.x;
        __shared__ float sw[CIN * 9];          // 18 KB
        const float* src = cw + (size_t)oc * (CIN * 9);
        for (int k = threadIdx.x; k < CIN * 9; k += 256) sw[k] = src[k];
        __syncthreads();
#pragma unroll
        for (int it = 0; it < 9; it++) {       // 2304 half2 = 9 taps x 256 pairs
            const int k = it * 256 + threadIdx.x;
            const int tap = k >> 8, ci = (k & 255) * 2;
            *(__half2*)&g_wt[((size_t)tap << 18) + ((size_t)oc << 9) + ci] =
                __floats2half2_rn(sw[ci * 9 + tap], sw[(ci + 1) * 9 + tap]);
        }
    } else if (blockIdx.x < WSPLIT_BLOCKS + DEMOD_BLOCKS) {
        const int oc = blockIdx.x - WSPLIT_BLOCKS;
        const int t = threadIdx.x;
        __shared__ float red[8][B];
        float acc[B];
#pragma unroll
        for (int b = 0; b < B; b++) acc[b] = 0.f;
        for (int i = t; i < CIN; i += 256) {
            const float* wp = cw + ((size_t)oc * CIN + i) * 9;
            float wsq = 0.f;
#pragma unroll
            for (int k = 0; k < 9; k++) { const float v = wp[k]; wsq += v * v; }
#pragma unroll
            for (int b = 0; b < B; b++) {
                const float s = g_s[b * CIN + i];
                acc[b] += wsq * s * s;
            }
        }
#pragma unroll
        for (int off = 16; off > 0; off >>= 1)
#pragma unroll
            for (int b = 0; b < B; b++)
                acc[b] += __shfl_down_sync(0xffffffffu, acc[b], off);
        const int warp = t >> 5, lane = t & 31;
        if (lane == 0)
#pragma unroll
            for (int b = 0; b < B; b++) red[warp][b] = acc[b];
        __syncthreads();
        if (t < B) {
            float v = 0.f;
#pragma unroll
            for (int w = 0; w < 8; w++) v += red[w][t];
            g_demod[t * COUT + oc] = rsqrtf(CONV_SCALE * CONV_SCALE * v + EPS);
        }
    } else {
        int i = blockIdx.x - WSPLIT_BLOCKS - DEMOD_BLOCKS;   // 0..4159
        int b = i / 260, r = i % 260;
        int h, w;
        if      (r <  66) { h = 0;           w = r;        }
        else if (r < 132) { h = 65;          w = r - 66;   }
        else if (r < 196) { h = r - 132 + 1; w = 0;        }
        else              { h = r - 196 + 1; w = 65;       }
        size_t base = (((size_t)b * XP + h) * XP + w) * CIN;
        *(uint32_t*)((char*)g_xs + base * 2 + threadIdx.x * 4) = 0u;
    }
}

// ---------------------------------------------------------------------------
// Kernel 3: transpose + scale:  xs[b][h+1][w+1][ci] = fp16(CONV_SCALE*s*x)
// float4 reads, __half2 stores.
// ---------------------------------------------------------------------------
__global__ __launch_bounds__(256) void xtrans_kernel(const float* __restrict__ x)
{
    const int cic = blockIdx.x, h = blockIdx.y, b = blockIdx.z;
    const int tid = threadIdx.x;
    const int ci0 = cic * 64;
    __shared__ float sT[64 * 65];
    __shared__ float sS[64];
    if (tid < 64) sS[tid] = CONV_SCALE * g_s[b * CIN + ci0 + tid];
#pragma unroll
    for (int it = 0; it < 4; it++) {           // 1024 float4 ops = 64 rows x 16
        int idx = it * 256 + tid;
        int cl = idx >> 4, wq = idx & 15;
        float4 v = *(const float4*)&x[(((size_t)(b * CIN + ci0 + cl)) * HH + h) * WW + wq * 4];
        float* d = &sT[cl * 65 + wq * 4];
        d[0] = v.x; d[1] = v.y; d[2] = v.z; d[3] = v.w;
    }
    __syncthreads();
#pragma unroll
    for (int it = 0; it < 8; it++) {           // 2048 half2 ops = 64 w x 32 pairs
        int idx = it * 256 + tid;
        int w = idx >> 5, clp = idx & 31;
        int cl = clp * 2;
        float v0 = sS[cl]     * sT[cl * 65 + w];
        float v1 = sS[cl + 1] * sT[(cl + 1) * 65 + w];
        size_t dst = (((size_t)b * XP + h + 1) * XP + (w + 1)) * CIN + ci0 + cl;
        *(__half2*)&g_xs[dst] = __floats2half2_rn(v0, v1);
    }
}

// ---------------------------------------------------------------------------
// Kernel 4: main wmma (HMMA) implicit-GEMM conv, warp-specialized pipeline.
// CTA: 128 oc x 256 px (4h x 64w). 10 warps: 0-7 compute (warp tile 64x64),
// 8-9 producers (cp.async.ca + mbarrier ring, 3 slots). No __syncthreads in
// loop. fp32 accum, demod in epilogue.   [best measured configuration]
// ---------------------------------------------------------------------------
#define LDM 72                           // 64 halves data + 8 pad (144B rows)
#define A_BYTES (128 * LDM * 2)          // 18432
#define B_BYTES (256 * LDM * 2)          // 36864
#define STAGE_BYTES (A_BYTES + B_BYTES)  // 55296
#define NSTAGE 3
#define SMEM_DYN (NSTAGE * STAGE_BYTES)  // 165888
#define NTHREADS 320

__global__ __launch_bounds__(NTHREADS, 1) void conv_wmma_kernel(float* __restrict__ out)
{
    extern __shared__ char dynsmem[];
    __shared__ __align__(8) uint64_t sh_mbar[2 * NSTAGE];  // full[3], empty[3]

    const int tid = threadIdx.x;
    const int wid = tid >> 5;
    const int lane = tid & 31;

    const int bx = blockIdx.x;    // 16 b x 16 h-groups(4h)
    const int b  = bx >> 4;
    const int h0 = (bx & 15) * 4;
    const int oc0 = blockIdx.y * 128;

    const uint32_t s_u32 = smem_u32(dynsmem);
    const uint32_t mb_u32 = smem_u32(&sh_mbar[0]);
    // full[s] at mb_u32 + s*8, empty[s] at mb_u32 + NSTAGE*8 + s*8

    if (tid == 0) {
#pragma unroll
        for (int s = 0; s < NSTAGE; s++) {
            MBAR_INIT(mb_u32 + s * 8, 64);                // full: 64 producer threads
            MBAR_INIT(mb_u32 + NSTAGE * 8 + s * 8, 8);    // empty: 8 compute warps
        }
    }
    __syncthreads();

    if (wid >= 8) {
        // ---------------- producers (warps 8-9, 64 threads) ----------------
        const int ptid = tid - 256;              // 0..63
        int slot = 0, par = 1;                   // phase-flip trick: first NSTAGE waits pass
        for (int iter = 0; iter < 72; iter++) {
            MBAR_WAIT(mb_u32 + NSTAGE * 8 + slot * 8, par);

            const int tap = iter >> 3;
            const int ci0 = (iter & 7) * 64;
            const int kh = tap / 3, kw = tap - 3 * kh;
            const uint32_t st = s_u32 + slot * STAGE_BYTES;
            const __half* wbase = g_wt + ((size_t)tap << 18) + ci0;
            const __half* xbase = g_xs + ((((size_t)b * XP) + h0 + kh) * XP + kw) * CIN + ci0;
#pragma unroll
            for (int j = 0; j < 48; j++) {
                const int op = j * 64 + ptid;
                uint32_t dst;
                const __half* src;
                if (j < 16) {                    // A: ops 0..1023 (compile-time split)
                    const int r = op >> 3, c = op & 7;
                    dst = st + r * 144 + c * 16;
                    src = wbase + ((size_t)(oc0 + r) << 9) + c * 8;
                } else {                         // B: ops 1024..3071
                    const int idx = op - 1024;
                    const int r = idx >> 3, c = idx & 7;
                    dst = st + A_BYTES + r * 144 + c * 16;
                    src = xbase + ((size_t)((r >> 6) * XP + (r & 63)) << 9) + c * 8;
                }
                asm volatile("cp.async.ca.shared.global [%0], [%1], 16;"
                             :: "r"(dst), "l"(src));
            }
            CPASYNC_MBAR_ARRIVE_NOINC(mb_u32 + slot * 8);

            slot++; if (slot == NSTAGE) { slot = 0; par ^= 1; }
        }
    } else {
        // ---------------- consumers (warps 0-7) ----------------
        const int wm = wid & 1;       // warp M block (64 oc)
        const int wn = wid >> 1;      // warp N block (64 px)

        wmma::fragment<wmma::accumulator, 16, 16, 16, float> c[4][4];
#pragma unroll
        for (int mt = 0; mt < 4; mt++)
#pragma unroll
            for (int nt = 0; nt < 4; nt++) wmma::fill_fragment(c[mt][nt], 0.f);

        int slot = 0, par = 0;
        for (int iter = 0; iter < 72; iter++) {
            MBAR_WAIT(mb_u32 + slot * 8, par);

            const char* st = dynsmem + slot * STAGE_BYTES;
            const __half* sA = (const __half*)(st);
            const __half* sB = (const __half*)(st + A_BYTES);

#pragma unroll
            for (int ks = 0; ks < 4; ks++) {
                wmma::fragment<wmma::matrix_b, 16, 16, 16, __half, wmma::col_major> bf[4];
#pragma unroll
                for (int nt = 0; nt < 4; nt++)
                    wmma::load_matrix_sync(bf[nt], sB + (wn * 64 + nt * 16) * LDM + ks * 16, LDM);
#pragma unroll
                for (int mt = 0; mt < 4; mt++) {
                    wmma::fragment<wmma::matrix_a, 16, 16, 16, __half, wmma::row_major> af;
                    wmma::load_matrix_sync(af, sA + (wm * 64 + mt * 16) * LDM + ks * 16, LDM);
#pragma unroll
                    for (int nt = 0; nt < 4; nt++)
                        wmma::mma_sync(c[mt][nt], af, bf[nt], c[mt][nt]);
                }
            }
            if (lane == 0) MBAR_ARRIVE(mb_u32 + NSTAGE * 8 + slot * 8);

            slot++; if (slot == NSTAGE) { slot = 0; par ^= 1; }
        }

        __syncthreads();   // join producers before smem reuse

        // epilogue part 1: accum -> SMEM [128 oc][260 px]
        float* ep = (float*)dynsmem;
#pragma unroll
        for (int mt = 0; mt < 4; mt++)
#pragma unroll
            for (int nt = 0; nt < 4; nt++)
                wmma::store_matrix_sync(ep + (wm * 64 + mt * 16) * 260 + wn * 64 + nt * 16,
                                        c[mt][nt], 260, wmma::mem_row_major);
        goto epilogue_join;
    }
    __syncthreads();       // producers join here (matches consumers' first sync)
epilogue_join:
    __syncthreads();       // everyone: ep fully written

    // epilogue part 2: demod-scaled coalesced STG, all 320 threads
    {
        const float* ep = (const float*)dynsmem;
        for (int idx = tid; idx < 128 * 256; idx += NTHREADS) {
            const int oc = idx >> 8, p = idx & 255;
            const float dm = g_demod[b * COUT + oc0 + oc];
            out[(((size_t)b * COUT + oc0 + oc) * HH + h0 + (p >> 6)) * WW + (p & 63)] =
                ep[oc * 260 + p] * dm;
        }
    }
}

// ---------------------------------------------------------------------------
extern "C" void kernel_launch(void* const* d_in, const int* in_sizes, int n_in,
                              void* d_out, int out_size)
{
    const float* input       = (const float*)d_in[0];
    const float* style       = (const float*)d_in[1];
    const float* conv_weight = (const float*)d_in[2];
    const float* mod_weight  = (const float*)d_in[3];
    const float* mod_bias    = (const float*)d_in[4];
    float* out = (float*)d_out;

    // 4-launch sequence: conv is launch #4 (ncu capture slot).
    mod_kernel<<<64, 256>>>(style, mod_weight, mod_bias);
    prep_kernel<<<WSPLIT_BLOCKS + DEMOD_BLOCKS + BORDER_BLOCKS, 256>>>(conv_weight);
    xtrans_kernel<<<dim3(8, 64, 16), 256>>>(input);

    cudaFuncSetAttribute(conv_wmma_kernel,
                         cudaFuncAttributeMaxDynamicSharedMemorySize, SMEM_DYN);
    conv_wmma_kernel<<<dim3(256, 4), NTHREADS, SMEM_DYN>>>(out);
}

// round 15
// speedup vs baseline: 1.0678x; 1.0602x over previous
#include <cuda_runtime.h>
#include <cuda_fp16.h>
#include <mma.h>
#include <math.h>
#include <stddef.h>
#include <stdint.h>

using namespace nvcuda;

#define B    16
#define CIN  512
#define COUT 512
#define HH   64
#define WW   64
#define SD   512
#define EPS  1e-8f

#define MOD_SCALE  0.04419417382415922f   // 1/sqrt(512)
#define CONV_SCALE 0.014731391274719738f  // 1/sqrt(512*9)

// padded, channel-last, scaled input: [B][66][66][512] fp16
#define XP 66
static __device__ __half g_xs[(size_t)B * XP * XP * CIN];
// weights channel-last per tap: [9][512 oc][512 ci] fp16
static __device__ __half g_wt[9 * COUT * CIN];
__device__ float g_s[B * CIN];
__device__ float g_demod[B * COUT];

__device__ __forceinline__ uint32_t smem_u32(const void* p) {
    uint32_t a;
    asm("{ .reg .u64 t; cvta.to.shared.u64 t, %1; cvt.u32.u64 %0, t; }"
        : "=r"(a) : "l"(p));
    return a;
}

#define MBAR_INIT(a, c) \
    asm volatile("mbarrier.init.shared.b64 [%0], %1;" :: "r"(a), "r"((uint32_t)(c)) : "memory")
#define MBAR_ARRIVE(a) \
    asm volatile("mbarrier.arrive.shared.b64 _, [%0];" :: "r"(a) : "memory")
#define MBAR_WAIT(a, ph) do {                                                        \
    asm volatile("{\n\t.reg .pred P1;\n\t"                                           \
        "WL%=:\n\tmbarrier.try_wait.parity.acquire.cta.shared::cta.b64 P1, [%0], %1, 0x989680;\n\t" \
        "@P1 bra.uni WD%=;\n\tbra.uni WL%=;\n\tWD%=:\n\t}"                           \
        :: "r"(a), "r"((uint32_t)(ph)) : "memory"); } while (0)
#define CPASYNC_MBAR_ARRIVE_NOINC(a) \
    asm volatile("cp.async.mbarrier.arrive.noinc.shared.b64 [%0];" :: "r"(a) : "memory")

// ---------------------------------------------------------------------------
// Kernel 1: s[b][i] = MOD_SCALE * (style[b,:] . mod_weight[i,:]) + mod_bias[i]
// ---------------------------------------------------------------------------
__global__ __launch_bounds__(256) void mod_kernel(
    const float* __restrict__ style, const float* __restrict__ mw,
    const float* __restrict__ mb)
{
    const int i0 = blockIdx.x * 8;
    const int t = threadIdx.x;
    __shared__ float sh_style[B * SD];   // 32 KB
    __shared__ float sh_w[8 * SD];       // 16 KB
    for (int idx = t; idx < B * SD; idx += 256) sh_style[idx] = style[idx];
    for (int idx = t; idx < 8 * SD; idx += 256)
        sh_w[idx] = mw[(size_t)i0 * SD + idx];
    __syncthreads();

    const int w = t >> 5, lane = t & 31;
    const int i = i0 + w;
    float acc[B];
#pragma unroll
    for (int b = 0; b < B; b++) acc[b] = 0.f;
    for (int d = lane; d < SD; d += 32) {
        const float wv = sh_w[w * SD + d];
#pragma unroll
        for (int b = 0; b < B; b++) acc[b] += wv * sh_style[b * SD + d];
    }
#pragma unroll
    for (int off = 16; off > 0; off >>= 1)
#pragma unroll
        for (int b = 0; b < B; b++)
            acc[b] += __shfl_down_sync(0xffffffffu, acc[b], off);
    if (lane == 0) {
        const float bias = mb[i];
#pragma unroll
        for (int b = 0; b < B; b++)
            g_s[b * CIN + i] = acc[b] * MOD_SCALE + bias;
    }
}

// ---------------------------------------------------------------------------
// Kernel 2 (fused): weight transpose + demod + borders. Runs AFTER mod.
// ---------------------------------------------------------------------------
#define WSPLIT_BLOCKS COUT                     // 512
#define DEMOD_BLOCKS  COUT                     // 512
#define BORDER_BLOCKS (B * 260)                // 4160
__global__ __launch_bounds__(256) void prep_kernel(const float* __restrict__ cw)
{
    if (blockIdx.x < WSPLIT_BLOCKS) {
        const int oc = blockIdx.x;
        __shared__ float sw[CIN * 9];          // 18 KB
        const float* src = cw + (size_t)oc * (CIN * 9);
        for (int k = threadIdx.x; k < CIN * 9; k += 256) sw[k] = src[k];
        __syncthreads();
#pragma unroll
        for (int it = 0; it < 9; it++) {
            const int k = it * 256 + threadIdx.x;
            const int tap = k >> 8, ci = (k & 255) * 2;
            *(__half2*)&g_wt[((size_t)tap << 18) + ((size_t)oc << 9) + ci] =
                __floats2half2_rn(sw[ci * 9 + tap], sw[(ci + 1) * 9 + tap]);
        }
    } else if (blockIdx.x < WSPLIT_BLOCKS + DEMOD_BLOCKS) {
        const int oc = blockIdx.x - WSPLIT_BLOCKS;
        const int t = threadIdx.x;
        __shared__ float red[8][B];
        float acc[B];
#pragma unroll
        for (int b = 0; b < B; b++) acc[b] = 0.f;
        for (int i = t; i < CIN; i += 256) {
            const float* wp = cw + ((size_t)oc * CIN + i) * 9;
            float wsq = 0.f;
#pragma unroll
            for (int k = 0; k < 9; k++) { const float v = wp[k]; wsq += v * v; }
#pragma unroll
            for (int b = 0; b < B; b++) {
                const float s = g_s[b * CIN + i];
                acc[b] += wsq * s * s;
            }
        }
#pragma unroll
        for (int off = 16; off > 0; off >>= 1)
#pragma unroll
            for (int b = 0; b < B; b++)
                acc[b] += __shfl_down_sync(0xffffffffu, acc[b], off);
        const int warp = t >> 5, lane = t & 31;
        if (lane == 0)
#pragma unroll
            for (int b = 0; b < B; b++) red[warp][b] = acc[b];
        __syncthreads();
        if (t < B) {
            float v = 0.f;
#pragma unroll
            for (int w = 0; w < 8; w++) v += red[w][t];
            g_demod[t * COUT + oc] = rsqrtf(CONV_SCALE * CONV_SCALE * v + EPS);
        }
    } else {
        int i = blockIdx.x - WSPLIT_BLOCKS - DEMOD_BLOCKS;   // 0..4159
        int b = i / 260, r = i % 260;
        int h, w;
        if      (r <  66) { h = 0;           w = r;        }
        else if (r < 132) { h = 65;          w = r - 66;   }
        else if (r < 196) { h = r - 132 + 1; w = 0;        }
        else              { h = r - 196 + 1; w = 65;       }
        size_t base = (((size_t)b * XP + h) * XP + w) * CIN;
        *(uint32_t*)((char*)g_xs + base * 2 + threadIdx.x * 4) = 0u;
    }
}

// ---------------------------------------------------------------------------
// Kernel 3: transpose + scale:  xs[b][h+1][w+1][ci] = fp16(CONV_SCALE*s*x)
// ---------------------------------------------------------------------------
__global__ __launch_bounds__(256) void xtrans_kernel(const float* __restrict__ x)
{
    const int cic = blockIdx.x, h = blockIdx.y, b = blockIdx.z;
    const int tid = threadIdx.x;
    const int ci0 = cic * 64;
    __shared__ float sT[64 * 65];
    __shared__ float sS[64];
    if (tid < 64) sS[tid] = CONV_SCALE * g_s[b * CIN + ci0 + tid];
#pragma unroll
    for (int it = 0; it < 4; it++) {
        int idx = it * 256 + tid;
        int cl = idx >> 4, wq = idx & 15;
        float4 v = *(const float4*)&x[(((size_t)(b * CIN + ci0 + cl)) * HH + h) * WW + wq * 4];
        float* d = &sT[cl * 65 + wq * 4];
        d[0] = v.x; d[1] = v.y; d[2] = v.z; d[3] = v.w;
    }
    __syncthreads();
#pragma unroll
    for (int it = 0; it < 8; it++) {
        int idx = it * 256 + tid;
        int w = idx >> 5, clp = idx & 31;
        int cl = clp * 2;
        float v0 = sS[cl]     * sT[cl * 65 + w];
        float v1 = sS[cl + 1] * sT[(cl + 1) * 65 + w];
        size_t dst = (((size_t)b * XP + h + 1) * XP + (w + 1)) * CIN + ci0 + cl;
        *(__half2*)&g_xs[dst] = __floats2half2_rn(v0, v1);
    }
}

// ---------------------------------------------------------------------------
// Kernel 4: main wmma (HMMA) implicit-GEMM conv, warp-specialized pipeline.
// CTA: 128 oc x 256 px (4h x 64w). 18 warps: 0-15 compute (warp tile 32x64,
// 4x4 split), 16-17 producers (cp.async + mbarrier ring, 3 slots).
// fp32 accum, demod in epilogue.  [R14 + occupancy: 10 -> 18 warps]
// ---------------------------------------------------------------------------
#define LDM 72                           // 64 halves data + 8 pad (144B rows)
#define A_BYTES (128 * LDM * 2)          // 18432
#define B_BYTES (256 * LDM * 2)          // 36864
#define STAGE_BYTES (A_BYTES + B_BYTES)  // 55296
#define NSTAGE 3
#define SMEM_DYN (NSTAGE * STAGE_BYTES)  // 165888
#define NTHREADS 576
#define NCWARPS 16

__global__ __launch_bounds__(NTHREADS, 1) void conv_wmma_kernel(float* __restrict__ out)
{
    extern __shared__ char dynsmem[];
    __shared__ __align__(8) uint64_t sh_mbar[2 * NSTAGE];  // full[3], empty[3]

    const int tid = threadIdx.x;
    const int wid = tid >> 5;
    const int lane = tid & 31;

    const int bx = blockIdx.x;    // 16 b x 16 h-groups(4h)
    const int b  = bx >> 4;
    const int h0 = (bx & 15) * 4;
    const int oc0 = blockIdx.y * 128;

    const uint32_t s_u32 = smem_u32(dynsmem);
    const uint32_t mb_u32 = smem_u32(&sh_mbar[0]);
    // full[s] at mb_u32 + s*8, empty[s] at mb_u32 + NSTAGE*8 + s*8

    if (tid == 0) {
#pragma unroll
        for (int s = 0; s < NSTAGE; s++) {
            MBAR_INIT(mb_u32 + s * 8, 64);                   // full: 64 producer threads
            MBAR_INIT(mb_u32 + NSTAGE * 8 + s * 8, NCWARPS); // empty: 16 compute warps
        }
    }
    __syncthreads();

    if (wid >= NCWARPS) {
        // ---------------- producers (warps 16-17, 64 threads) ----------------
        const int ptid = tid - NCWARPS * 32;     // 0..63
        int slot = 0, par = 1;                   // phase-flip trick: first NSTAGE waits pass
        for (int iter = 0; iter < 72; iter++) {
            MBAR_WAIT(mb_u32 + NSTAGE * 8 + slot * 8, par);

            const int tap = iter >> 3;
            const int ci0 = (iter & 7) * 64;
            const int kh = tap / 3, kw = tap - 3 * kh;
            const uint32_t st = s_u32 + slot * STAGE_BYTES;
            const __half* wbase = g_wt + ((size_t)tap << 18) + ci0;
            const __half* xbase = g_xs + ((((size_t)b * XP) + h0 + kh) * XP + kw) * CIN + ci0;
#pragma unroll
            for (int j = 0; j < 48; j++) {
                const int op = j * 64 + ptid;
                uint32_t dst;
                const __half* src;
                if (j < 16) {                    // A: ops 0..1023 (compile-time split)
                    const int r = op >> 3, c = op & 7;
                    dst = st + r * 144 + c * 16;
                    src = wbase + ((size_t)(oc0 + r) << 9) + c * 8;
                } else {                         // B: ops 1024..3071
                    const int idx = op - 1024;
                    const int r = idx >> 3, c = idx & 7;
                    dst = st + A_BYTES + r * 144 + c * 16;
                    src = xbase + ((size_t)((r >> 6) * XP + (r & 63)) << 9) + c * 8;
                }
                asm volatile("cp.async.ca.shared.global [%0], [%1], 16;"
                             :: "r"(dst), "l"(src));
            }
            CPASYNC_MBAR_ARRIVE_NOINC(mb_u32 + slot * 8);

            slot++; if (slot == NSTAGE) { slot = 0; par ^= 1; }
        }
    } else {
        // ---------------- consumers (warps 0-15) ----------------
        const int wm = wid & 3;       // warp M block (32 oc)
        const int wn = wid >> 2;      // warp N block (64 px)

        wmma::fragment<wmma::accumulator, 16, 16, 16, float> c[2][4];
#pragma unroll
        for (int mt = 0; mt < 2; mt++)
#pragma unroll
            for (int nt = 0; nt < 4; nt++) wmma::fill_fragment(c[mt][nt], 0.f);

        int slot = 0, par = 0;
        for (int iter = 0; iter < 72; iter++) {
            MBAR_WAIT(mb_u32 + slot * 8, par);

            const char* st = dynsmem + slot * STAGE_BYTES;
            const __half* sA = (const __half*)(st);
            const __half* sB = (const __half*)(st + A_BYTES);

#pragma unroll
            for (int ks = 0; ks < 4; ks++) {
                wmma::fragment<wmma::matrix_b, 16, 16, 16, __half, wmma::col_major> bf[4];
#pragma unroll
                for (int nt = 0; nt < 4; nt++)
                    wmma::load_matrix_sync(bf[nt], sB + (wn * 64 + nt * 16) * LDM + ks * 16, LDM);
#pragma unroll
                for (int mt = 0; mt < 2; mt++) {
                    wmma::fragment<wmma::matrix_a, 16, 16, 16, __half, wmma::row_major> af;
                    wmma::load_matrix_sync(af, sA + (wm * 32 + mt * 16) * LDM + ks * 16, LDM);
#pragma unroll
                    for (int nt = 0; nt < 4; nt++)
                        wmma::mma_sync(c[mt][nt], af, bf[nt], c[mt][nt]);
                }
            }
            if (lane == 0) MBAR_ARRIVE(mb_u32 + NSTAGE * 8 + slot * 8);

            slot++; if (slot == NSTAGE) { slot = 0; par ^= 1; }
        }

        __syncthreads();   // join producers before smem reuse

        // epilogue part 1: accum -> SMEM [128 oc][260 px]
        float* ep = (float*)dynsmem;
#pragma unroll
        for (int mt = 0; mt < 2; mt++)
#pragma unroll
            for (int nt = 0; nt < 4; nt++)
                wmma::store_matrix_sync(ep + (wm * 32 + mt * 16) * 260 + wn * 64 + nt * 16,
                                        c[mt][nt], 260, wmma::mem_row_major);
        goto epilogue_join;
    }
    __syncthreads();       // producers join here (matches consumers' first sync)
epilogue_join:
    __syncthreads();       // everyone: ep fully written

    // epilogue part 2: demod-scaled coalesced STG, all 576 threads
    {
        const float* ep = (const float*)dynsmem;
        for (int idx = tid; idx < 128 * 256; idx += NTHREADS) {
            const int oc = idx >> 8, p = idx & 255;
            const float dm = g_demod[b * COUT + oc0 + oc];
            out[(((size_t)b * COUT + oc0 + oc) * HH + h0 + (p >> 6)) * WW + (p & 63)] =
                ep[oc * 260 + p] * dm;
        }
    }
}

// ---------------------------------------------------------------------------
extern "C" void kernel_launch(void* const* d_in, const int* in_sizes, int n_in,
                              void* d_out, int out_size)
{
    const float* input       = (const float*)d_in[0];
    const float* style       = (const float*)d_in[1];
    const float* conv_weight = (const float*)d_in[2];
    const float* mod_weight  = (const float*)d_in[3];
    const float* mod_bias    = (const float*)d_in[4];
    float* out = (float*)d_out;

    // 4-launch sequence: conv is launch #4 (ncu capture slot).
    mod_kernel<<<64, 256>>>(style, mod_weight, mod_bias);
    prep_kernel<<<WSPLIT_BLOCKS + DEMOD_BLOCKS + BORDER_BLOCKS, 256>>>(conv_weight);
    xtrans_kernel<<<dim3(8, 64, 16), 256>>>(input);

    cudaFuncSetAttribute(conv_wmma_kernel,
                         cudaFuncAttributeMaxDynamicSharedMemorySize, SMEM_DYN);
    conv_wmma_kernel<<<dim3(256, 4), NTHREADS, SMEM_DYN>>>(out);
}

// round 16
// speedup vs baseline: 1.0895x; 1.0203x over previous
#include <cuda_runtime.h>
#include <cuda_fp16.h>
#include <mma.h>
#include <math.h>
#include <stddef.h>
#include <stdint.h>

using namespace nvcuda;

#define B    16
#define CIN  512
#define COUT 512
#define HH   64
#define WW   64
#define SD   512
#define EPS  1e-8f

#define MOD_SCALE  0.04419417382415922f   // 1/sqrt(512)
#define CONV_SCALE 0.014731391274719738f  // 1/sqrt(512*9)

// padded, channel-last, scaled input: [B][66][66][512] fp16
#define XP 66
static __device__ __half g_xs[(size_t)B * XP * XP * CIN];
// weights channel-last per tap: [9][512 oc][512 ci] fp16
static __device__ __half g_wt[9 * COUT * CIN];
__device__ float g_s[B * CIN];
__device__ float g_demod[B * COUT];

__device__ __forceinline__ uint32_t smem_u32(const void* p) {
    uint32_t a;
    asm("{ .reg .u64 t; cvta.to.shared.u64 t, %1; cvt.u32.u64 %0, t; }"
        : "=r"(a) : "l"(p));
    return a;
}

#define MBAR_INIT(a, c) \
    asm volatile("mbarrier.init.shared.b64 [%0], %1;" :: "r"(a), "r"((uint32_t)(c)) : "memory")
#define MBAR_ARRIVE(a) \
    asm volatile("mbarrier.arrive.shared.b64 _, [%0];" :: "r"(a) : "memory")
#define MBAR_WAIT(a, ph) do {                                                        \
    asm volatile("{\n\t.reg .pred P1;\n\t"                                           \
        "WL%=:\n\tmbarrier.try_wait.parity.acquire.cta.shared::cta.b64 P1, [%0], %1, 0x989680;\n\t" \
        "@P1 bra.uni WD%=;\n\tbra.uni WL%=;\n\tWD%=:\n\t}"                           \
        :: "r"(a), "r"((uint32_t)(ph)) : "memory"); } while (0)
#define CPASYNC_MBAR_ARRIVE_NOINC(a) \
    asm volatile("cp.async.mbarrier.arrive.noinc.shared.b64 [%0];" :: "r"(a) : "memory")

// ---------------------------------------------------------------------------
// Kernel 1: s[b][i] = MOD_SCALE * (style[b,:] . mod_weight[i,:]) + mod_bias[i]
// ---------------------------------------------------------------------------
__global__ __launch_bounds__(256) void mod_kernel(
    const float* __restrict__ style, const float* __restrict__ mw,
    const float* __restrict__ mb)
{
    const int i0 = blockIdx.x * 8;
    const int t = threadIdx.x;
    __shared__ float sh_style[B * SD];   // 32 KB
    __shared__ float sh_w[8 * SD];       // 16 KB
    for (int idx = t; idx < B * SD; idx += 256) sh_style[idx] = style[idx];
    for (int idx = t; idx < 8 * SD; idx += 256)
        sh_w[idx] = mw[(size_t)i0 * SD + idx];
    __syncthreads();

    const int w = t >> 5, lane = t & 31;
    const int i = i0 + w;
    float acc[B];
#pragma unroll
    for (int b = 0; b < B; b++) acc[b] = 0.f;
    for (int d = lane; d < SD; d += 32) {
        const float wv = sh_w[w * SD + d];
#pragma unroll
        for (int b = 0; b < B; b++) acc[b] += wv * sh_style[b * SD + d];
    }
#pragma unroll
    for (int off = 16; off > 0; off >>= 1)
#pragma unroll
        for (int b = 0; b < B; b++)
            acc[b] += __shfl_down_sync(0xffffffffu, acc[b], off);
    if (lane == 0) {
        const float bias = mb[i];
#pragma unroll
        for (int b = 0; b < B; b++)
            g_s[b * CIN + i] = acc[b] * MOD_SCALE + bias;
    }
}

// ---------------------------------------------------------------------------
// Kernel 2 (fused): weight transpose + demod + borders. Runs AFTER mod.
// ---------------------------------------------------------------------------
#define WSPLIT_BLOCKS COUT                     // 512
#define DEMOD_BLOCKS  COUT                     // 512
#define BORDER_BLOCKS (B * 260)                // 4160
__global__ __launch_bounds__(256) void prep_kernel(const float* __restrict__ cw)
{
    if (blockIdx.x < WSPLIT_BLOCKS) {
        const int oc = blockIdx.x;
        __shared__ float sw[CIN * 9];          // 18 KB
        const float* src = cw + (size_t)oc * (CIN * 9);
        for (int k = threadIdx.x; k < CIN * 9; k += 256) sw[k] = src[k];
        __syncthreads();
#pragma unroll
        for (int it = 0; it < 9; it++) {
            const int k = it * 256 + threadIdx.x;
            const int tap = k >> 8, ci = (k & 255) * 2;
            *(__half2*)&g_wt[((size_t)tap << 18) + ((size_t)oc << 9) + ci] =
                __floats2half2_rn(sw[ci * 9 + tap], sw[(ci + 1) * 9 + tap]);
        }
    } else if (blockIdx.x < WSPLIT_BLOCKS + DEMOD_BLOCKS) {
        const int oc = blockIdx.x - WSPLIT_BLOCKS;
        const int t = threadIdx.x;
        __shared__ float red[8][B];
        float acc[B];
#pragma unroll
        for (int b = 0; b < B; b++) acc[b] = 0.f;
        for (int i = t; i < CIN; i += 256) {
            const float* wp = cw + ((size_t)oc * CIN + i) * 9;
            float wsq = 0.f;
#pragma unroll
            for (int k = 0; k < 9; k++) { const float v = wp[k]; wsq += v * v; }
#pragma unroll
            for (int b = 0; b < B; b++) {
                const float s = g_s[b * CIN + i];
                acc[b] += wsq * s * s;
            }
        }
#pragma unroll
        for (int off = 16; off > 0; off >>= 1)
#pragma unroll
            for (int b = 0; b < B; b++)
                acc[b] += __shfl_down_sync(0xffffffffu, acc[b], off);
        const int warp = t >> 5, lane = t & 31;
        if (lane == 0)
#pragma unroll
            for (int b = 0; b < B; b++) red[warp][b] = acc[b];
        __syncthreads();
        if (t < B) {
            float v = 0.f;
#pragma unroll
            for (int w = 0; w < 8; w++) v += red[w][t];
            g_demod[t * COUT + oc] = rsqrtf(CONV_SCALE * CONV_SCALE * v + EPS);
        }
    } else {
        int i = blockIdx.x - WSPLIT_BLOCKS - DEMOD_BLOCKS;   // 0..4159
        int b = i / 260, r = i % 260;
        int h, w;
        if      (r <  66) { h = 0;           w = r;        }
        else if (r < 132) { h = 65;          w = r - 66;   }
        else if (r < 196) { h = r - 132 + 1; w = 0;        }
        else              { h = r - 196 + 1; w = 65;       }
        size_t base = (((size_t)b * XP + h) * XP + w) * CIN;
        *(uint32_t*)((char*)g_xs + base * 2 + threadIdx.x * 4) = 0u;
    }
}

// ---------------------------------------------------------------------------
// Kernel 3: transpose + scale:  xs[b][h+1][w+1][ci] = fp16(CONV_SCALE*s*x)
// ---------------------------------------------------------------------------
__global__ __launch_bounds__(256) void xtrans_kernel(const float* __restrict__ x)
{
    const int cic = blockIdx.x, h = blockIdx.y, b = blockIdx.z;
    const int tid = threadIdx.x;
    const int ci0 = cic * 64;
    __shared__ float sT[64 * 65];
    __shared__ float sS[64];
    if (tid < 64) sS[tid] = CONV_SCALE * g_s[b * CIN + ci0 + tid];
#pragma unroll
    for (int it = 0; it < 4; it++) {
        int idx = it * 256 + tid;
        int cl = idx >> 4, wq = idx & 15;
        float4 v = *(const float4*)&x[(((size_t)(b * CIN + ci0 + cl)) * HH + h) * WW + wq * 4];
        float* d = &sT[cl * 65 + wq * 4];
        d[0] = v.x; d[1] = v.y; d[2] = v.z; d[3] = v.w;
    }
    __syncthreads();
#pragma unroll
    for (int it = 0; it < 8; it++) {
        int idx = it * 256 + tid;
        int w = idx >> 5, clp = idx & 31;
        int cl = clp * 2;
        float v0 = sS[cl]     * sT[cl * 65 + w];
        float v1 = sS[cl + 1] * sT[(cl + 1) * 65 + w];
        size_t dst = (((size_t)b * XP + h + 1) * XP + (w + 1)) * CIN + ci0 + cl;
        *(__half2*)&g_xs[dst] = __floats2half2_rn(v0, v1);
    }
}

// ---------------------------------------------------------------------------
// Kernel 4: main wmma (HMMA) implicit-GEMM conv, warp-specialized pipeline.
// CTA: 128 oc x 256 px (4h x 64w). 19 warps: 0-15 compute (warp tile 32x64),
// 16-18 producers (96 threads, cp.async + mbarrier ring, 3 slots).
// Consumer signals empty EARLY (after last LDSM of stage, before final MMAs).
// fp32 accum, demod in epilogue.
// ---------------------------------------------------------------------------
#define LDM 72                           // 64 halves data + 8 pad (144B rows)
#define A_BYTES (128 * LDM * 2)          // 18432
#define B_BYTES (256 * LDM * 2)          // 36864
#define STAGE_BYTES (A_BYTES + B_BYTES)  // 55296
#define NSTAGE 3
#define SMEM_DYN (NSTAGE * STAGE_BYTES)  // 165888
#define NCWARPS 16
#define NPTHREADS 96
#define NTHREADS (NCWARPS * 32 + NPTHREADS)   // 608

__global__ __launch_bounds__(NTHREADS, 1) void conv_wmma_kernel(float* __restrict__ out)
{
    extern __shared__ char dynsmem[];
    __shared__ __align__(8) uint64_t sh_mbar[2 * NSTAGE];  // full[3], empty[3]

    const int tid = threadIdx.x;
    const int wid = tid >> 5;
    const int lane = tid & 31;

    const int bx = blockIdx.x;    // 16 b x 16 h-groups(4h)
    const int b  = bx >> 4;
    const int h0 = (bx & 15) * 4;
    const int oc0 = blockIdx.y * 128;

    const uint32_t s_u32 = smem_u32(dynsmem);
    const uint32_t mb_u32 = smem_u32(&sh_mbar[0]);
    // full[s] at mb_u32 + s*8, empty[s] at mb_u32 + NSTAGE*8 + s*8

    if (tid == 0) {
#pragma unroll
        for (int s = 0; s < NSTAGE; s++) {
            MBAR_INIT(mb_u32 + s * 8, NPTHREADS);            // full: 96 producer threads
            MBAR_INIT(mb_u32 + NSTAGE * 8 + s * 8, NCWARPS); // empty: 16 compute warps
        }
    }
    __syncthreads();

    if (wid >= NCWARPS) {
        // ---------------- producers (warps 16-18, 96 threads) ----------------
        const int ptid = tid - NCWARPS * 32;     // 0..95
        int slot = 0, par = 1;                   // phase-flip trick: first NSTAGE waits pass
        for (int iter = 0; iter < 72; iter++) {
            MBAR_WAIT(mb_u32 + NSTAGE * 8 + slot * 8, par);

            const int tap = iter >> 3;
            const int ci0 = (iter & 7) * 64;
            const int kh = tap / 3, kw = tap - 3 * kh;
            const uint32_t st = s_u32 + slot * STAGE_BYTES;
            const __half* wbase = g_wt + ((size_t)tap << 18) + ci0;
            const __half* xbase = g_xs + ((((size_t)b * XP) + h0 + kh) * XP + kw) * CIN + ci0;
#pragma unroll
            for (int j = 0; j < 32; j++) {       // 3072 cp.async total / 96 thr
                const int op = j * NPTHREADS + ptid;
                uint32_t dst;
                const __half* src;
                if (op < 1024) {                 // A: 128 rows x 8 chunks
                    const int r = op >> 3, c = op & 7;
                    dst = st + r * 144 + c * 16;
                    src = wbase + ((size_t)(oc0 + r) << 9) + c * 8;
                } else {                         // B: 256 rows x 8 chunks
                    const int idx = op - 1024;
                    const int r = idx >> 3, c = idx & 7;
                    dst = st + A_BYTES + r * 144 + c * 16;
                    src = xbase + ((size_t)((r >> 6) * XP + (r & 63)) << 9) + c * 8;
                }
                asm volatile("cp.async.ca.shared.global [%0], [%1], 16;"
                             :: "r"(dst), "l"(src));
            }
            CPASYNC_MBAR_ARRIVE_NOINC(mb_u32 + slot * 8);

            slot++; if (slot == NSTAGE) { slot = 0; par ^= 1; }
        }
    } else {
        // ---------------- consumers (warps 0-15) ----------------
        const int wm = wid & 3;       // warp M block (32 oc)
        const int wn = wid >> 2;      // warp N block (64 px)

        wmma::fragment<wmma::accumulator, 16, 16, 16, float> c[2][4];
#pragma unroll
        for (int mt = 0; mt < 2; mt++)
#pragma unroll
            for (int nt = 0; nt < 4; nt++) wmma::fill_fragment(c[mt][nt], 0.f);

        int slot = 0, par = 0;
        for (int iter = 0; iter < 72; iter++) {
            MBAR_WAIT(mb_u32 + slot * 8, par);

            const char* st = dynsmem + slot * STAGE_BYTES;
            const __half* sA = (const __half*)(st);
            const __half* sB = (const __half*)(st + A_BYTES);

#pragma unroll
            for (int ks = 0; ks < 3; ks++) {
                wmma::fragment<wmma::matrix_b, 16, 16, 16, __half, wmma::col_major> bf[4];
#pragma unroll
                for (int nt = 0; nt < 4; nt++)
                    wmma::load_matrix_sync(bf[nt], sB + (wn * 64 + nt * 16) * LDM + ks * 16, LDM);
#pragma unroll
                for (int mt = 0; mt < 2; mt++) {
                    wmma::fragment<wmma::matrix_a, 16, 16, 16, __half, wmma::row_major> af;
                    wmma::load_matrix_sync(af, sA + (wm * 32 + mt * 16) * LDM + ks * 16, LDM);
#pragma unroll
                    for (int nt = 0; nt < 4; nt++)
                        wmma::mma_sync(c[mt][nt], af, bf[nt], c[mt][nt]);
                }
            }
            // ks = 3: load ALL fragments first, signal empty early, then MMA.
            {
                wmma::fragment<wmma::matrix_b, 16, 16, 16, __half, wmma::col_major> bf[4];
#pragma unroll
                for (int nt = 0; nt < 4; nt++)
                    wmma::load_matrix_sync(bf[nt], sB + (wn * 64 + nt * 16) * LDM + 48, LDM);
                wmma::fragment<wmma::matrix_a, 16, 16, 16, __half, wmma::row_major> af0, af1;
                wmma::load_matrix_sync(af0, sA + (wm * 32) * LDM + 48, LDM);
                wmma::load_matrix_sync(af1, sA + (wm * 32 + 16) * LDM + 48, LDM);

                if (lane == 0) MBAR_ARRIVE(mb_u32 + NSTAGE * 8 + slot * 8);  // early

#pragma unroll
                for (int nt = 0; nt < 4; nt++) wmma::mma_sync(c[0][nt], af0, bf[nt], c[0][nt]);
#pragma unroll
                for (int nt = 0; nt < 4; nt++) wmma::mma_sync(c[1][nt], af1, bf[nt], c[1][nt]);
            }

            slot++; if (slot == NSTAGE) { slot = 0; par ^= 1; }
        }

        __syncthreads();   // join producers before smem reuse

        // epilogue part 1: accum -> SMEM [128 oc][260 px]
        float* ep = (float*)dynsmem;
#pragma unroll
        for (int mt = 0; mt < 2; mt++)
#pragma unroll
            for (int nt = 0; nt < 4; nt++)
                wmma::store_matrix_sync(ep + (wm * 32 + mt * 16) * 260 + wn * 64 + nt * 16,
                                        c[mt][nt], 260, wmma::mem_row_major);
        goto epilogue_join;
    }
    __syncthreads();       // producers join here (matches consumers' first sync)
epilogue_join:
    __syncthreads();       // everyone: ep fully written

    // epilogue part 2: demod-scaled coalesced STG, all 608 threads
    {
        const float* ep = (const float*)dynsmem;
        for (int idx = tid; idx < 128 * 256; idx += NTHREADS) {
            const int oc = idx >> 8, p = idx & 255;
            const float dm = g_demod[b * COUT + oc0 + oc];
            out[(((size_t)b * COUT + oc0 + oc) * HH + h0 + (p >> 6)) * WW + (p & 63)] =
                ep[oc * 260 + p] * dm;
        }
    }
}

// ---------------------------------------------------------------------------
extern "C" void kernel_launch(void* const* d_in, const int* in_sizes, int n_in,
                              void* d_out, int out_size)
{
    const float* input       = (const float*)d_in[0];
    const float* style       = (const float*)d_in[1];
    const float* conv_weight = (const float*)d_in[2];
    const float* mod_weight  = (const float*)d_in[3];
    const float* mod_bias    = (const float*)d_in[4];
    float* out = (float*)d_out;

    // 4-launch sequence: conv is launch #4 (ncu capture slot).
    mod_kernel<<<64, 256>>>(style, mod_weight, mod_bias);
    prep_kernel<<<WSPLIT_BLOCKS + DEMOD_BLOCKS + BORDER_BLOCKS, 256>>>(conv_weight);
    xtrans_kernel<<<dim3(8, 64, 16), 256>>>(input);

    cudaFuncSetAttribute(conv_wmma_kernel,
                         cudaFuncAttributeMaxDynamicSharedMemorySize, SMEM_DYN);
    conv_wmma_kernel<<<dim3(256, 4), NTHREADS, SMEM_DYN>>>(out);
}

// round 17
// speedup vs baseline: 1.0955x; 1.0055x over previous
#include <cuda_runtime.h>
#include <cuda_fp16.h>
#include <mma.h>
#include <math.h>
#include <stddef.h>
#include <stdint.h>

using namespace nvcuda;

#define B    16
#define CIN  512
#define COUT 512
#define HH   64
#define WW   64
#define SD   512
#define EPS  1e-8f

#define MOD_SCALE  0.04419417382415922f   // 1/sqrt(512)
#define CONV_SCALE 0.014731391274719738f  // 1/sqrt(512*9)

// padded, channel-last, scaled input: [B][66][66][512] fp16
#define XP 66
static __device__ __half g_xs[(size_t)B * XP * XP * CIN];
// weights channel-last per tap: [9][512 oc][512 ci] fp16
static __device__ __half g_wt[9 * COUT * CIN];
__device__ float g_s[B * CIN];
__device__ float g_demod[B * COUT];

__device__ __forceinline__ uint32_t smem_u32(const void* p) {
    uint32_t a;
    asm("{ .reg .u64 t; cvta.to.shared.u64 t, %1; cvt.u32.u64 %0, t; }"
        : "=r"(a) : "l"(p));
    return a;
}

#define MBAR_INIT(a, c) \
    asm volatile("mbarrier.init.shared.b64 [%0], %1;" :: "r"(a), "r"((uint32_t)(c)) : "memory")
#define MBAR_ARRIVE(a) \
    asm volatile("mbarrier.arrive.shared.b64 _, [%0];" :: "r"(a) : "memory")
#define MBAR_WAIT(a, ph) do {                                                        \
    asm volatile("{\n\t.reg .pred P1;\n\t"                                           \
        "WL%=:\n\tmbarrier.try_wait.parity.acquire.cta.shared::cta.b64 P1, [%0], %1, 0x989680;\n\t" \
        "@P1 bra.uni WD%=;\n\tbra.uni WL%=;\n\tWD%=:\n\t}"                           \
        :: "r"(a), "r"((uint32_t)(ph)) : "memory"); } while (0)
#define CPASYNC_MBAR_ARRIVE_NOINC(a) \
    asm volatile("cp.async.mbarrier.arrive.noinc.shared.b64 [%0];" :: "r"(a) : "memory")

// ---------------------------------------------------------------------------
// Kernel 1 (fused, all independent): mod + weight transpose + borders.
// Blocks [0, 64):          mod — s[b][i] = MOD_SCALE*(style.mw[i]) + mb[i]
// Blocks [64, 576):        wsplit per oc (SMEM-staged, coalesced)
// Blocks [576, 576+4160):  zero one 512-ch border row of g_xs
// ---------------------------------------------------------------------------
#define MOD_BLOCKS    64
#define WSPLIT_BLOCKS COUT                     // 512
#define BORDER_BLOCKS (B * 260)                // 4160
__global__ __launch_bounds__(256) void prep1_kernel(
    const float* __restrict__ style, const float* __restrict__ mw,
    const float* __restrict__ mb, const float* __restrict__ cw)
{
    __shared__ float buf[12288];               // 48 KB shared scratch
    if (blockIdx.x < MOD_BLOCKS) {
        const int i0 = blockIdx.x * 8;
        const int t = threadIdx.x;
        float* sh_style = buf;                 // 8192 floats
        float* sh_w = buf + B * SD;            // 4096 floats
        for (int idx = t; idx < B * SD; idx += 256) sh_style[idx] = style[idx];
        for (int idx = t; idx < 8 * SD; idx += 256)
            sh_w[idx] = mw[(size_t)i0 * SD + idx];
        __syncthreads();

        const int w = t >> 5, lane = t & 31;
        const int i = i0 + w;
        float acc[B];
#pragma unroll
        for (int b = 0; b < B; b++) acc[b] = 0.f;
        for (int d = lane; d < SD; d += 32) {
            const float wv = sh_w[w * SD + d];
#pragma unroll
            for (int b = 0; b < B; b++) acc[b] += wv * sh_style[b * SD + d];
        }
#pragma unroll
        for (int off = 16; off > 0; off >>= 1)
#pragma unroll
            for (int b = 0; b < B; b++)
                acc[b] += __shfl_down_sync(0xffffffffu, acc[b], off);
        if (lane == 0) {
            const float bias = mb[i];
#pragma unroll
            for (int b = 0; b < B; b++)
                g_s[b * CIN + i] = acc[b] * MOD_SCALE + bias;
        }
    } else if (blockIdx.x < MOD_BLOCKS + WSPLIT_BLOCKS) {
        const int oc = blockIdx.x - MOD_BLOCKS;
        float* sw = buf;                       // 4608 floats = 18 KB
        const float* src = cw + (size_t)oc * (CIN * 9);
        for (int k = threadIdx.x; k < CIN * 9; k += 256) sw[k] = src[k];
        __syncthreads();
#pragma unroll
        for (int it = 0; it < 9; it++) {
            const int k = it * 256 + threadIdx.x;
            const int tap = k >> 8, ci = (k & 255) * 2;
            *(__half2*)&g_wt[((size_t)tap << 18) + ((size_t)oc << 9) + ci] =
                __floats2half2_rn(sw[ci * 9 + tap], sw[(ci + 1) * 9 + tap]);
        }
    } else {
        int i = blockIdx.x - MOD_BLOCKS - WSPLIT_BLOCKS;   // 0..4159
        int b = i / 260, r = i % 260;
        int h, w;
        if      (r <  66) { h = 0;           w = r;        }
        else if (r < 132) { h = 65;          w = r - 66;   }
        else if (r < 196) { h = r - 132 + 1; w = 0;        }
        else              { h = r - 196 + 1; w = 65;       }
        size_t base = (((size_t)b * XP + h) * XP + w) * CIN;
        *(uint32_t*)((char*)g_xs + base * 2 + threadIdx.x * 4) = 0u;
    }
}

// ---------------------------------------------------------------------------
// Kernel 2 (fused, both depend only on g_s): demod + xtrans.
// Blocks [0, 512):        demod per oc
// Blocks [512, 512+8192): xtrans — xs[b][h+1][w+1][ci] = fp16(CONV_SCALE*s*x)
// ---------------------------------------------------------------------------
#define DEMOD_BLOCKS COUT                      // 512
__global__ __launch_bounds__(256) void prep2_kernel(
    const float* __restrict__ cw, const float* __restrict__ x)
{
    __shared__ float buf[64 * 65 + 64 + 64];
    if (blockIdx.x < DEMOD_BLOCKS) {
        const int oc = blockIdx.x;
        const int t = threadIdx.x;
        float (*red)[B] = (float (*)[B])buf;
        float acc[B];
#pragma unroll
        for (int b = 0; b < B; b++) acc[b] = 0.f;
        for (int i = t; i < CIN; i += 256) {
            const float* wp = cw + ((size_t)oc * CIN + i) * 9;
            float wsq = 0.f;
#pragma unroll
            for (int k = 0; k < 9; k++) { const float v = wp[k]; wsq += v * v; }
#pragma unroll
            for (int b = 0; b < B; b++) {
                const float s = g_s[b * CIN + i];
                acc[b] += wsq * s * s;
            }
        }
#pragma unroll
        for (int off = 16; off > 0; off >>= 1)
#pragma unroll
            for (int b = 0; b < B; b++)
                acc[b] += __shfl_down_sync(0xffffffffu, acc[b], off);
        const int warp = t >> 5, lane = t & 31;
        if (lane == 0)
#pragma unroll
            for (int b = 0; b < B; b++) red[warp][b] = acc[b];
        __syncthreads();
        if (t < B) {
            float v = 0.f;
#pragma unroll
            for (int w = 0; w < 8; w++) v += red[w][t];
            g_demod[t * COUT + oc] = rsqrtf(CONV_SCALE * CONV_SCALE * v + EPS);
        }
    } else {
        const int bi = blockIdx.x - DEMOD_BLOCKS;   // 0..8191: cic + 8*(h + 64*b)
        const int cic = bi & 7;
        const int h = (bi >> 3) & 63;
        const int b = bi >> 9;
        const int tid = threadIdx.x;
        const int ci0 = cic * 64;
        float* sT = buf;               // 64*65
        float* sS = buf + 64 * 65;     // 64
        if (tid < 64) sS[tid] = CONV_SCALE * g_s[b * CIN + ci0 + tid];
#pragma unroll
        for (int it = 0; it < 4; it++) {
            int idx = it * 256 + tid;
            int cl = idx >> 4, wq = idx & 15;
            float4 v = *(const float4*)&x[(((size_t)(b * CIN + ci0 + cl)) * HH + h) * WW + wq * 4];
            float* d = &sT[cl * 65 + wq * 4];
            d[0] = v.x; d[1] = v.y; d[2] = v.z; d[3] = v.w;
        }
        __syncthreads();
#pragma unroll
        for (int it = 0; it < 8; it++) {
            int idx = it * 256 + tid;
            int w = idx >> 5, clp = idx & 31;
            int cl = clp * 2;
            float v0 = sS[cl]     * sT[cl * 65 + w];
            float v1 = sS[cl + 1] * sT[(cl + 1) * 65 + w];
            size_t dst = (((size_t)b * XP + h + 1) * XP + (w + 1)) * CIN + ci0 + cl;
            *(__half2*)&g_xs[dst] = __floats2half2_rn(v0, v1);
        }
    }
}

// ---------------------------------------------------------------------------
// Kernel 3: main wmma (HMMA) implicit-GEMM conv, warp-specialized pipeline.
// CTA: 128 oc x 256 px (4h x 64w). 19 warps: 0-15 compute (warp tile 32x64),
// 16-18 producers (96 threads, cp.async + mbarrier ring, 3 slots).
// Early empty-arrive after last LDSM of each stage. fp32 accum, demod epilogue.
// [R16 exact configuration]
// ---------------------------------------------------------------------------
#define LDM 72                           // 64 halves data + 8 pad (144B rows)
#define A_BYTES (128 * LDM * 2)          // 18432
#define B_BYTES (256 * LDM * 2)          // 36864
#define STAGE_BYTES (A_BYTES + B_BYTES)  // 55296
#define NSTAGE 3
#define SMEM_DYN (NSTAGE * STAGE_BYTES)  // 165888
#define NCWARPS 16
#define NPTHREADS 96
#define NTHREADS (NCWARPS * 32 + NPTHREADS)   // 608

__global__ __launch_bounds__(NTHREADS, 1) void conv_wmma_kernel(float* __restrict__ out)
{
    extern __shared__ char dynsmem[];
    __shared__ __align__(8) uint64_t sh_mbar[2 * NSTAGE];  // full[3], empty[3]

    const int tid = threadIdx.x;
    const int wid = tid >> 5;
    const int lane = tid & 31;

    const int bx = blockIdx.x;    // 16 b x 16 h-groups(4h)
    const int b  = bx >> 4;
    const int h0 = (bx & 15) * 4;
    const int oc0 = blockIdx.y * 128;

    const uint32_t s_u32 = smem_u32(dynsmem);
    const uint32_t mb_u32 = smem_u32(&sh_mbar[0]);
    // full[s] at mb_u32 + s*8, empty[s] at mb_u32 + NSTAGE*8 + s*8

    if (tid == 0) {
#pragma unroll
        for (int s = 0; s < NSTAGE; s++) {
            MBAR_INIT(mb_u32 + s * 8, NPTHREADS);            // full: 96 producer threads
            MBAR_INIT(mb_u32 + NSTAGE * 8 + s * 8, NCWARPS); // empty: 16 compute warps
        }
    }
    __syncthreads();

    if (wid >= NCWARPS) {
        // ---------------- producers (warps 16-18, 96 threads) ----------------
        const int ptid = tid - NCWARPS * 32;     // 0..95
        int slot = 0, par = 1;                   // phase-flip trick: first NSTAGE waits pass
        for (int iter = 0; iter < 72; iter++) {
            MBAR_WAIT(mb_u32 + NSTAGE * 8 + slot * 8, par);

            const int tap = iter >> 3;
            const int ci0 = (iter & 7) * 64;
            const int kh = tap / 3, kw = tap - 3 * kh;
            const uint32_t st = s_u32 + slot * STAGE_BYTES;
            const __half* wbase = g_wt + ((size_t)tap << 18) + ci0;
            const __half* xbase = g_xs + ((((size_t)b * XP) + h0 + kh) * XP + kw) * CIN + ci0;
#pragma unroll
            for (int j = 0; j < 32; j++) {       // 3072 cp.async total / 96 thr
                const int op = j * NPTHREADS + ptid;
                uint32_t dst;
                const __half* src;
                if (op < 1024) {                 // A: 128 rows x 8 chunks
                    const int r = op >> 3, c = op & 7;
                    dst = st + r * 144 + c * 16;
                    src = wbase + ((size_t)(oc0 + r) << 9) + c * 8;
                } else {                         // B: 256 rows x 8 chunks
                    const int idx = op - 1024;
                    const int r = idx >> 3, c = idx & 7;
                    dst = st + A_BYTES + r * 144 + c * 16;
                    src = xbase + ((size_t)((r >> 6) * XP + (r & 63)) << 9) + c * 8;
                }
                asm volatile("cp.async.ca.shared.global [%0], [%1], 16;"
                             :: "r"(dst), "l"(src));
            }
            CPASYNC_MBAR_ARRIVE_NOINC(mb_u32 + slot * 8);

            slot++; if (slot == NSTAGE) { slot = 0; par ^= 1; }
        }
    } else {
        // ---------------- consumers (warps 0-15) ----------------
        const int wm = wid & 3;       // warp M block (32 oc)
        const int wn = wid >> 2;      // warp N block (64 px)

        wmma::fragment<wmma::accumulator, 16, 16, 16, float> c[2][4];
#pragma unroll
        for (int mt = 0; mt < 2; mt++)
#pragma unroll
            for (int nt = 0; nt < 4; nt++) wmma::fill_fragment(c[mt][nt], 0.f);

        int slot = 0, par = 0;
        for (int iter = 0; iter < 72; iter++) {
            MBAR_WAIT(mb_u32 + slot * 8, par);

            const char* st = dynsmem + slot * STAGE_BYTES;
            const __half* sA = (const __half*)(st);
            const __half* sB = (const __half*)(st + A_BYTES);

#pragma unroll
            for (int ks = 0; ks < 3; ks++) {
                wmma::fragment<wmma::matrix_b, 16, 16, 16, __half, wmma::col_major> bf[4];
#pragma unroll
                for (int nt = 0; nt < 4; nt++)
                    wmma::load_matrix_sync(bf[nt], sB + (wn * 64 + nt * 16) * LDM + ks * 16, LDM);
#pragma unroll
                for (int mt = 0; mt < 2; mt++) {
                    wmma::fragment<wmma::matrix_a, 16, 16, 16, __half, wmma::row_major> af;
                    wmma::load_matrix_sync(af, sA + (wm * 32 + mt * 16) * LDM + ks * 16, LDM);
#pragma unroll
                    for (int nt = 0; nt < 4; nt++)
                        wmma::mma_sync(c[mt][nt], af, bf[nt], c[mt][nt]);
                }
            }
            // ks = 3: load ALL fragments first, signal empty early, then MMA.
            {
                wmma::fragment<wmma::matrix_b, 16, 16, 16, __half, wmma::col_major> bf[4];
#pragma unroll
                for (int nt = 0; nt < 4; nt++)
                    wmma::load_matrix_sync(bf[nt], sB + (wn * 64 + nt * 16) * LDM + 48, LDM);
                wmma::fragment<wmma::matrix_a, 16, 16, 16, __half, wmma::row_major> af0, af1;
                wmma::load_matrix_sync(af0, sA + (wm * 32) * LDM + 48, LDM);
                wmma::load_matrix_sync(af1, sA + (wm * 32 + 16) * LDM + 48, LDM);

                if (lane == 0) MBAR_ARRIVE(mb_u32 + NSTAGE * 8 + slot * 8);  // early

#pragma unroll
                for (int nt = 0; nt < 4; nt++) wmma::mma_sync(c[0][nt], af0, bf[nt], c[0][nt]);
#pragma unroll
                for (int nt = 0; nt < 4; nt++) wmma::mma_sync(c[1][nt], af1, bf[nt], c[1][nt]);
            }

            slot++; if (slot == NSTAGE) { slot = 0; par ^= 1; }
        }

        __syncthreads();   // join producers before smem reuse

        // epilogue part 1: accum -> SMEM [128 oc][260 px]
        float* ep = (float*)dynsmem;
#pragma unroll
        for (int mt = 0; mt < 2; mt++)
#pragma unroll
            for (int nt = 0; nt < 4; nt++)
                wmma::store_matrix_sync(ep + (wm * 32 + mt * 16) * 260 + wn * 64 + nt * 16,
                                        c[mt][nt], 260, wmma::mem_row_major);
        goto epilogue_join;
    }
    __syncthreads();       // producers join here (matches consumers' first sync)
epilogue_join:
    __syncthreads();       // everyone: ep fully written

    // epilogue part 2: demod-scaled coalesced STG, all 608 threads
    {
        const float* ep = (const float*)dynsmem;
        for (int idx = tid; idx < 128 * 256; idx += NTHREADS) {
            const int oc = idx >> 8, p = idx & 255;
            const float dm = g_demod[b * COUT + oc0 + oc];
            out[(((size_t)b * COUT + oc0 + oc) * HH + h0 + (p >> 6)) * WW + (p & 63)] =
                ep[oc * 260 + p] * dm;
        }
    }
}

// ---------------------------------------------------------------------------
extern "C" void kernel_launch(void* const* d_in, const int* in_sizes, int n_in,
                              void* d_out, int out_size)
{
    const float* input       = (const float*)d_in[0];
    const float* style       = (const float*)d_in[1];
    const float* conv_weight = (const float*)d_in[2];
    const float* mod_weight  = (const float*)d_in[3];
    const float* mod_bias    = (const float*)d_in[4];
    float* out = (float*)d_out;

    // 3-launch sequence: dependency-fused prep.
    prep1_kernel<<<MOD_BLOCKS + WSPLIT_BLOCKS + BORDER_BLOCKS, 256>>>(
        style, mod_weight, mod_bias, conv_weight);
    prep2_kernel<<<DEMOD_BLOCKS + 8192, 256>>>(conv_weight, input);

    cudaFuncSetAttribute(conv_wmma_kernel,
                         cudaFuncAttributeMaxDynamicSharedMemorySize, SMEM_DYN);
    conv_wmma_kernel<<<dim3(256, 4), NTHREADS, SMEM_DYN>>>(out);
}